// round 8
// baseline (speedup 1.0000x reference)
#include <cuda_runtime.h>
#include <cuda_bf16.h>
#include <math.h>
#include <stdint.h>

#define RES_H 512
#define RES_W 512
#define NPTS (RES_H * RES_W)
#define MAX_VAL 100.0f
#define N_ITERS 5
#define TWO_PI 6.28318530717958647692f

#define KPAD 136                 // padded K stride in bf16 elems
#define ROWB (KPAD * 2)          // 272 bytes per row
#define HALF_BYTES (128 * ROWB)  // one hi or lo image: 34816 B
#define LAYER_BYTES (2 * HALF_BYTES)
#define DYN_BYTES (3 * LAYER_BYTES + 128)

// ---------------- scratch ----------------
__device__ float g_Cs[NPTS];
__device__ float g_V[2][NPTS];
// pre-transposed, hi/lo split, K-padded weights: [layer][hi/lo][n=128][KPAD]
__device__ __align__(16) __nv_bfloat16 g_Wp[4 * 2 * 128 * KPAD];

// ---------------- helpers ----------------
__device__ __forceinline__ uint32_t smem_u32(const void* p) {
    uint32_t a;
    asm("{ .reg .u64 t; cvta.to.shared.u64 t, %1; cvt.u32.u64 %0, t; }" : "=r"(a) : "l"(p));
    return a;
}
__device__ __forceinline__ void sts32(uint32_t a, uint32_t v) {
    asm volatile("st.shared.b32 [%0], %1;" :: "r"(a), "r"(v) : "memory");
}
__device__ __forceinline__ uint32_t pack_bf16x2(float lo, float hi) {
    uint32_t r;
    asm("cvt.rn.bf16x2.f32 %0, %1, %2;" : "=r"(r) : "f"(hi), "f"(lo));
    return r;
}
__device__ __forceinline__ float lo_f(uint32_t hp) { return __uint_as_float(hp << 16); }
__device__ __forceinline__ float hi_f(uint32_t hp) { return __uint_as_float(hp & 0xffff0000u); }

__device__ __forceinline__ void cp16(uint32_t dst, const void* src) {
    asm volatile("cp.async.cg.shared.global [%0], [%1], 16;" :: "r"(dst), "l"(src) : "memory");
}
#define CP_COMMIT() asm volatile("cp.async.commit_group;" ::: "memory")
#define CP_WAIT(n)  asm volatile("cp.async.wait_group %0;" :: "n"(n) : "memory")

__device__ __forceinline__ void ldsm4(uint32_t (&r)[4], uint32_t addr) {
    asm volatile("ldmatrix.sync.aligned.m8n8.x4.shared.b16 {%0,%1,%2,%3}, [%4];"
                 : "=r"(r[0]), "=r"(r[1]), "=r"(r[2]), "=r"(r[3]) : "r"(addr));
}
__device__ __forceinline__ void mma16816(float (&c)[4], const uint32_t (&a)[4],
                                         const uint32_t* b) {
    asm volatile(
        "mma.sync.aligned.m16n8k16.row.col.f32.bf16.bf16.f32 "
        "{%0,%1,%2,%3}, {%4,%5,%6,%7}, {%8,%9}, {%0,%1,%2,%3};"
        : "+f"(c[0]), "+f"(c[1]), "+f"(c[2]), "+f"(c[3])
        : "r"(a[0]), "r"(a[1]), "r"(a[2]), "r"(a[3]), "r"(b[0]), "r"(b[1]));
}

// ---------------- weight prep: transpose + hi/lo split + K-pad ----------------
__global__ void prepw_kernel(const float* __restrict__ Wh) {
    int idx = blockIdx.x * blockDim.x + threadIdx.x;
    if (idx >= 4 * 128 * 128) return;
    int k = idx & 127, n = (idx >> 7) & 127, l = idx >> 14;
    float w = Wh[l * 16384 + k * 128 + n];
    __nv_bfloat16 hi = __float2bfloat16(w);
    float lo = w - __bfloat162float(hi);
    g_Wp[((size_t)(l * 2 + 0) * 128 + n) * KPAD + k] = hi;
    g_Wp[((size_t)(l * 2 + 1) * 128 + n) * KPAD + k] = __float2bfloat16(lo);
}

// ---------------- MLP via warp-level bf16 mma.sync (3-term split) ----------------
// CTA: 256 thr (8 warps = 4M x 2N), M=128 pts, N=128, K=128.
// dyn SMEM: [A_hi 34816][A_lo 34816][Wbuf0 69632][Wbuf1 69632]
__global__ void __launch_bounds__(256, 1)
mlp_mma_kernel(const float* __restrict__ x, const float* __restrict__ B_enc,
               const float* __restrict__ W_out, float* __restrict__ C_out)
{
    extern __shared__ uint8_t dsm[];
    __shared__ float sBe[128], sWo[128], sRed[128];

    const int tid = threadIdx.x;
    const int lid = tid & 31;
    const int wid = tid >> 5;
    const int warpm = wid & 3;   // M group (32 rows)
    const int warpn = wid >> 2;  // N group (64 cols)

    const uint32_t sbase = (smem_u32(dsm) + 127u) & ~127u;
    const uint32_t Ahi = sbase;
    const uint32_t Alo = sbase + HALF_BYTES;
    const uint32_t wbuf0 = sbase + LAYER_BYTES;

    if (tid < 128) { sBe[tid] = B_enc[tid]; sWo[tid] = W_out[tid]; }
    __syncthreads();

    // kick layer-0 weight load (overlaps encoding)
    {
        const uint8_t* src = (const uint8_t*)g_Wp;
        for (int i = tid; i < LAYER_BYTES / 16; i += 256)
            cp16(wbuf0 + (uint32_t)i * 16, src + i * 16);
        CP_COMMIT();
    }

    // ---- encoding: enc[p][f] = cos, enc[p][64+f] = sin; hi/lo split ----
    const int p0 = blockIdx.x * 128;
    {
        const float2* x2 = (const float2*)x;
        int p = tid >> 1;
        int fh = (tid & 1) << 5;
        float2 xv = x2[p0 + p];
        float xa = 0.5f + 0.5f * xv.x;
        float xb = 0.5f + 0.5f * xv.y;
        uint32_t rowb = (uint32_t)p * ROWB;
        #pragma unroll
        for (int f2 = 0; f2 < 32; f2 += 2) {
            int f = fh + f2;
            float vp0 = TWO_PI * (xa * sBe[2 * f]     + xb * sBe[2 * f + 1]);
            float vp1 = TWO_PI * (xa * sBe[2 * f + 2] + xb * sBe[2 * f + 3]);
            float s0, c0, s1, c1;
            __sincosf(vp0, &s0, &c0);
            __sincosf(vp1, &s1, &c1);
            uint32_t offc = rowb + (uint32_t)f * 2;
            uint32_t hp = pack_bf16x2(c0, c1);
            sts32(Ahi + offc, hp);
            sts32(Alo + offc, pack_bf16x2(c0 - lo_f(hp), c1 - hi_f(hp)));
            uint32_t offs = rowb + (uint32_t)(64 + f) * 2;
            uint32_t hp2 = pack_bf16x2(s0, s1);
            sts32(Ahi + offs, hp2);
            sts32(Alo + offs, pack_bf16x2(s0 - lo_f(hp2), s1 - hi_f(hp2)));
        }
    }

    // per-lane ldmatrix base offsets (layout-invariant)
    uint32_t aoff[2], boff[4];
    #pragma unroll
    for (int mt = 0; mt < 2; mt++)
        aoff[mt] = (uint32_t)(warpm * 32 + mt * 16 + (lid & 15)) * ROWB + ((lid >> 4) << 4);
    #pragma unroll
    for (int q = 0; q < 4; q++)
        boff[q] = (uint32_t)(warpn * 64 + q * 16 + ((lid >> 4) << 3) + (lid & 7)) * ROWB
                + (((lid >> 3) & 1) << 4);

    #pragma unroll 1
    for (int l = 0; l < 4; l++) {
        uint32_t wb = wbuf0 + (uint32_t)(l & 1) * LAYER_BYTES;
        if (l < 3) {  // prefetch next layer's weights
            const uint8_t* src = (const uint8_t*)(g_Wp + (size_t)(l + 1) * 2 * 128 * KPAD);
            uint32_t dst = wbuf0 + (uint32_t)((l + 1) & 1) * LAYER_BYTES;
            for (int i = tid; i < LAYER_BYTES / 16; i += 256)
                cp16(dst + (uint32_t)i * 16, src + i * 16);
            CP_COMMIT();
            CP_WAIT(1);
        } else {
            CP_WAIT(0);
        }
        __syncthreads();  // weights ready; prev epilogue STS / encoding visible

        float acc[2][8][4];
        #pragma unroll
        for (int mt = 0; mt < 2; mt++)
            #pragma unroll
            for (int nt = 0; nt < 8; nt++)
                #pragma unroll
                for (int j = 0; j < 4; j++) acc[mt][nt][j] = 0.0f;

        #pragma unroll 1
        for (int ps = 0; ps < 3; ps++) {  // hi*hi, lo*hi, hi*lo
            uint32_t Ab = (ps == 1) ? Alo : Ahi;
            uint32_t Wb = wb + ((ps == 2) ? (uint32_t)HALF_BYTES : 0u);
            #pragma unroll
            for (int ks = 0; ks < 8; ks++) {
                uint32_t af[2][4], bf[4][4];
                ldsm4(af[0], Ab + aoff[0] + (uint32_t)ks * 32);
                ldsm4(af[1], Ab + aoff[1] + (uint32_t)ks * 32);
                #pragma unroll
                for (int q = 0; q < 4; q++)
                    ldsm4(bf[q], Wb + boff[q] + (uint32_t)ks * 32);
                #pragma unroll
                for (int mt = 0; mt < 2; mt++)
                    #pragma unroll
                    for (int nt = 0; nt < 8; nt++)
                        mma16816(acc[mt][nt], af[mt], &bf[nt >> 1][(nt & 1) * 2]);
            }
        }
        __syncthreads();  // all reads of A done before overwrite

        if (l < 3) {
            // ReLU + hi/lo split back into A
            #pragma unroll
            for (int mt = 0; mt < 2; mt++) {
                uint32_t r0 = (uint32_t)(warpm * 32 + mt * 16 + (lid >> 2));
                #pragma unroll
                for (int nt = 0; nt < 8; nt++) {
                    uint32_t cb = (uint32_t)(warpn * 64 + nt * 8 + (lid & 3) * 2) * 2;
                    uint32_t off = r0 * ROWB + cb;
                    float h0 = fmaxf(acc[mt][nt][0], 0.0f);
                    float h1 = fmaxf(acc[mt][nt][1], 0.0f);
                    uint32_t hp = pack_bf16x2(h0, h1);
                    sts32(Ahi + off, hp);
                    sts32(Alo + off, pack_bf16x2(h0 - lo_f(hp), h1 - hi_f(hp)));
                    float h2 = fmaxf(acc[mt][nt][2], 0.0f);
                    float h3 = fmaxf(acc[mt][nt][3], 0.0f);
                    uint32_t off8 = off + 8 * ROWB;
                    uint32_t hp2 = pack_bf16x2(h2, h3);
                    sts32(Ahi + off8, hp2);
                    sts32(Alo + off8, pack_bf16x2(h2 - lo_f(hp2), h3 - hi_f(hp2)));
                }
            }
        } else {
            // fused final layer: C = relu(h) . W_out
            float v[4] = {0.f, 0.f, 0.f, 0.f};
            #pragma unroll
            for (int mt = 0; mt < 2; mt++)
                #pragma unroll
                for (int nt = 0; nt < 8; nt++) {
                    int n = warpn * 64 + nt * 8 + (lid & 3) * 2;
                    float w0 = sWo[n], w1 = sWo[n + 1];
                    v[mt * 2]     += fmaxf(acc[mt][nt][0], 0.f) * w0
                                   + fmaxf(acc[mt][nt][1], 0.f) * w1;
                    v[mt * 2 + 1] += fmaxf(acc[mt][nt][2], 0.f) * w0
                                   + fmaxf(acc[mt][nt][3], 0.f) * w1;
                }
            #pragma unroll
            for (int i = 0; i < 4; i++) {
                v[i] += __shfl_xor_sync(0xffffffffu, v[i], 1);
                v[i] += __shfl_xor_sync(0xffffffffu, v[i], 2);
            }
            int rbase = warpm * 32 + (lid >> 2);
            if (warpn == 0 && (lid & 3) == 0) {
                sRed[rbase]      = v[0];
                sRed[rbase + 8]  = v[1];
                sRed[rbase + 16] = v[2];
                sRed[rbase + 24] = v[3];
            }
            __syncthreads();
            if (warpn == 1 && (lid & 3) == 0) {
                C_out[p0 + rbase]      = sRed[rbase]      + v[0];
                C_out[p0 + rbase + 8]  = sRed[rbase + 8]  + v[1];
                C_out[p0 + rbase + 16] = sRed[rbase + 16] + v[2];
                C_out[p0 + rbase + 24] = sRed[rbase + 24] + v[3];
            }
        }
    }
}

// ---------------- prep: V0, obj box filter, Cs ----------------
__global__ void prep_kernel(const int* __restrict__ bt,
                            const float* __restrict__ bc,
                            const float* __restrict__ C)
{
    int p = blockIdx.x * blockDim.x + threadIdx.x;
    if (p >= NPTS) return;
    int y = p >> 9;
    int xx = p & 511;
    bool is_free = (bt[p] == 0);

    float extra = 0.0f;
    if (is_free) {
        float sum = 0.0f;
        #pragma unroll
        for (int dy = -2; dy <= 2; dy++) {
            int yy = y + dy;
            if (yy < 0 || yy >= RES_H) continue;
            #pragma unroll
            for (int dx = -2; dx <= 2; dx++) {
                int xn = xx + dx;
                if (xn < 0 || xn >= RES_W) continue;
                int q = yy * RES_W + xn;
                int b = bt[q];
                float v = bc[q];
                if (b == 1 && v > 0.0f) sum += v;
            }
        }
        extra = sum * (1.0f / 25.0f);
    }
    g_Cs[p] = fmaxf(C[p], 0.0f) + extra;
    g_V[0][p] = is_free ? MAX_VAL : bc[p];
}

// ---------------- Jacobi stencil pass ----------------
__global__ void jacobi_kernel(int src,
                              const int* __restrict__ bt,
                              const float* __restrict__ bc)
{
    int p = blockIdx.x * blockDim.x + threadIdx.x;
    if (p >= NPTS) return;
    const float* __restrict__ Vin = g_V[src];
    float* __restrict__ Vout = g_V[1 - src];

    if (bt[p] != 0) { Vout[p] = bc[p]; return; }

    int y = p >> 9;
    int xx = p & 511;
    int ym = max(y - 1, 0), yp = min(y + 1, RES_H - 1);
    int xm = max(xx - 1, 0), xp = min(xx + 1, RES_W - 1);
    float nb = Vin[ym * RES_W + xm] + Vin[ym * RES_W + xx] + Vin[ym * RES_W + xp]
             + Vin[y  * RES_W + xm]                        + Vin[y  * RES_W + xp]
             + Vin[yp * RES_W + xm] + Vin[yp * RES_W + xx] + Vin[yp * RES_W + xp];
    Vout[p] = nb * 0.125f + g_Cs[p];
}

// ---------------- bilinear grid sample ----------------
__global__ void sample_kernel(const float* __restrict__ x,
                              float* __restrict__ out)
{
    int p = blockIdx.x * blockDim.x + threadIdx.x;
    if (p >= NPTS) return;
    const float* __restrict__ V = g_V[1];

    float gx = x[2 * p];
    float gy = x[2 * p + 1];
    float ix = fminf(fmaxf((gx + 1.0f) * 0.5f * (RES_W - 1), 0.0f), (float)(RES_W - 1));
    float iy = fminf(fmaxf((gy + 1.0f) * 0.5f * (RES_H - 1), 0.0f), (float)(RES_H - 1));
    int x0 = (int)floorf(ix);
    int y0 = (int)floorf(iy);
    int x1 = min(x0 + 1, RES_W - 1);
    int y1 = min(y0 + 1, RES_H - 1);
    float wx = ix - (float)x0;
    float wy = iy - (float)y0;

    float v00 = V[y0 * RES_W + x0];
    float v01 = V[y0 * RES_W + x1];
    float v10 = V[y1 * RES_W + x0];
    float v11 = V[y1 * RES_W + x1];
    out[p] = v00 * (1.0f - wx) * (1.0f - wy) + v01 * wx * (1.0f - wy)
           + v10 * (1.0f - wx) * wy + v11 * wx * wy;
}

// ---------------- launch ----------------
extern "C" void kernel_launch(void* const* d_in, const int* in_sizes, int n_in,
                              void* d_out, int out_size)
{
    const float* x    = (const float*)d_in[0];
    const int*   bt   = (const int*)  d_in[1];
    const float* bc   = (const float*)d_in[2];
    const float* Benc = (const float*)d_in[3];
    const float* Wh   = (const float*)d_in[4];
    const float* Wout = (const float*)d_in[5];

    float* out  = (float*)d_out;
    float* Cout = out + NPTS;

    cudaFuncSetAttribute(mlp_mma_kernel, cudaFuncAttributeMaxDynamicSharedMemorySize, DYN_BYTES);

    prepw_kernel<<<256, 256>>>(Wh);
    mlp_mma_kernel<<<NPTS / 128, 256, DYN_BYTES>>>(x, Benc, Wout, Cout);
    prep_kernel<<<NPTS / 256, 256>>>(bt, bc, Cout);
    for (int i = 0; i < N_ITERS; i++)
        jacobi_kernel<<<NPTS / 256, 256>>>(i & 1, bt, bc);
    sample_kernel<<<NPTS / 256, 256>>>(x, out);
}

// round 10
// speedup vs baseline: 1.5446x; 1.5446x over previous
#include <cuda_runtime.h>
#include <cuda_bf16.h>
#include <math.h>
#include <stdint.h>

#define RES_H 512
#define RES_W 512
#define NPTS (RES_H * RES_W)
#define MAX_VAL 100.0f
#define N_ITERS 5
#define TWO_PI 6.28318530717958647692f

#define KPAD 136                 // padded K stride in bf16 elems
#define ROWB (KPAD * 2)          // 272 bytes per row
#define HALF_BYTES (128 * ROWB)  // one hi or lo image: 34816 B
#define LAYER_BYTES (2 * HALF_BYTES)
#define DYN_BYTES (3 * LAYER_BYTES + 128)

// ---------------- scratch ----------------
__device__ float g_Cs[NPTS];
__device__ float g_V[2][NPTS];
// pre-transposed, hi/lo split, K-padded weights: [layer][hi/lo][n=128][KPAD]
__device__ __align__(16) __nv_bfloat16 g_Wp[4 * 2 * 128 * KPAD];

// ---------------- helpers ----------------
__device__ __forceinline__ uint32_t smem_u32(const void* p) {
    uint32_t a;
    asm("{ .reg .u64 t; cvta.to.shared.u64 t, %1; cvt.u32.u64 %0, t; }" : "=r"(a) : "l"(p));
    return a;
}
__device__ __forceinline__ void sts32(uint32_t a, uint32_t v) {
    asm volatile("st.shared.b32 [%0], %1;" :: "r"(a), "r"(v) : "memory");
}
__device__ __forceinline__ uint32_t pack_bf16x2(float lo, float hi) {
    uint32_t r;
    asm("cvt.rn.bf16x2.f32 %0, %1, %2;" : "=r"(r) : "f"(hi), "f"(lo));
    return r;
}
__device__ __forceinline__ float lo_f(uint32_t hp) { return __uint_as_float(hp << 16); }
__device__ __forceinline__ float hi_f(uint32_t hp) { return __uint_as_float(hp & 0xffff0000u); }

__device__ __forceinline__ void cp16(uint32_t dst, const void* src) {
    asm volatile("cp.async.cg.shared.global [%0], [%1], 16;" :: "r"(dst), "l"(src) : "memory");
}
#define CP_COMMIT() asm volatile("cp.async.commit_group;" ::: "memory")
#define CP_WAIT(n)  asm volatile("cp.async.wait_group %0;" :: "n"(n) : "memory")

__device__ __forceinline__ void ldsm4(uint32_t (&r)[4], uint32_t addr) {
    asm volatile("ldmatrix.sync.aligned.m8n8.x4.shared.b16 {%0,%1,%2,%3}, [%4];"
                 : "=r"(r[0]), "=r"(r[1]), "=r"(r[2]), "=r"(r[3]) : "r"(addr));
}
__device__ __forceinline__ void mma16816(float (&c)[4], const uint32_t (&a)[4],
                                         const uint32_t* b) {
    asm volatile(
        "mma.sync.aligned.m16n8k16.row.col.f32.bf16.bf16.f32 "
        "{%0,%1,%2,%3}, {%4,%5,%6,%7}, {%8,%9}, {%0,%1,%2,%3};"
        : "+f"(c[0]), "+f"(c[1]), "+f"(c[2]), "+f"(c[3])
        : "r"(a[0]), "r"(a[1]), "r"(a[2]), "r"(a[3]), "r"(b[0]), "r"(b[1]));
}

// ---------------- weight prep: transpose + hi/lo split + K-pad ----------------
__global__ void prepw_kernel(const float* __restrict__ Wh) {
    int idx = blockIdx.x * blockDim.x + threadIdx.x;
    if (idx >= 4 * 128 * 128) return;
    int k = idx & 127, n = (idx >> 7) & 127, l = idx >> 14;
    float w = Wh[l * 16384 + k * 128 + n];
    __nv_bfloat16 hi = __float2bfloat16(w);
    float lo = w - __bfloat162float(hi);
    g_Wp[((size_t)(l * 2 + 0) * 128 + n) * KPAD + k] = hi;
    g_Wp[((size_t)(l * 2 + 1) * 128 + n) * KPAD + k] = __float2bfloat16(lo);
}

// ---------------- MLP via warp-level bf16 mma.sync (3-term split) ----------------
// CTA: 256 thr (8 warps = 4M x 2N), M=128 pts, N=128, K=128.
// dyn SMEM: [A_hi 34816][A_lo 34816][Wbuf0 69632][Wbuf1 69632]
__global__ void __launch_bounds__(256, 1)
mlp_mma_kernel(const float* __restrict__ x, const float* __restrict__ B_enc,
               const float* __restrict__ W_out, float* __restrict__ C_out)
{
    extern __shared__ uint8_t dsm[];
    __shared__ float sBe[128], sWo[128], sRed[128];

    const int tid = threadIdx.x;
    const int lid = tid & 31;
    const int wid = tid >> 5;
    const int warpm = wid & 3;   // M group (32 rows)
    const int warpn = wid >> 2;  // N group (64 cols)

    const uint32_t sbase = (smem_u32(dsm) + 127u) & ~127u;
    const uint32_t Ahi = sbase;
    const uint32_t Alo = sbase + HALF_BYTES;
    const uint32_t wbuf0 = sbase + LAYER_BYTES;

    if (tid < 128) { sBe[tid] = B_enc[tid]; sWo[tid] = W_out[tid]; }
    __syncthreads();

    // kick layer-0 weight load (overlaps encoding)
    {
        const uint8_t* src = (const uint8_t*)g_Wp;
        for (int i = tid; i < LAYER_BYTES / 16; i += 256)
            cp16(wbuf0 + (uint32_t)i * 16, src + i * 16);
        CP_COMMIT();
    }

    // ---- encoding: enc[p][f] = cos, enc[p][64+f] = sin; hi/lo split ----
    const int p0 = blockIdx.x * 128;
    {
        const float2* x2 = (const float2*)x;
        int p = tid >> 1;
        int fh = (tid & 1) << 5;
        float2 xv = x2[p0 + p];
        float xa = 0.5f + 0.5f * xv.x;
        float xb = 0.5f + 0.5f * xv.y;
        uint32_t rowb = (uint32_t)p * ROWB;
        #pragma unroll
        for (int f2 = 0; f2 < 32; f2 += 2) {
            int f = fh + f2;
            float vp0 = TWO_PI * (xa * sBe[2 * f]     + xb * sBe[2 * f + 1]);
            float vp1 = TWO_PI * (xa * sBe[2 * f + 2] + xb * sBe[2 * f + 3]);
            float s0, c0, s1, c1;
            __sincosf(vp0, &s0, &c0);
            __sincosf(vp1, &s1, &c1);
            uint32_t offc = rowb + (uint32_t)f * 2;
            uint32_t hp = pack_bf16x2(c0, c1);
            sts32(Ahi + offc, hp);
            sts32(Alo + offc, pack_bf16x2(c0 - lo_f(hp), c1 - hi_f(hp)));
            uint32_t offs = rowb + (uint32_t)(64 + f) * 2;
            uint32_t hp2 = pack_bf16x2(s0, s1);
            sts32(Ahi + offs, hp2);
            sts32(Alo + offs, pack_bf16x2(s0 - lo_f(hp2), s1 - hi_f(hp2)));
        }
    }

    // per-lane ldmatrix base offsets (layout-invariant)
    uint32_t aoff[2], boff[4];
    #pragma unroll
    for (int mt = 0; mt < 2; mt++)
        aoff[mt] = (uint32_t)(warpm * 32 + mt * 16 + (lid & 15)) * ROWB + ((lid >> 4) << 4);
    #pragma unroll
    for (int q = 0; q < 4; q++)
        boff[q] = (uint32_t)(warpn * 64 + q * 16 + ((lid >> 4) << 3) + (lid & 7)) * ROWB
                + (((lid >> 3) & 1) << 4);

    #pragma unroll 1
    for (int l = 0; l < 4; l++) {
        uint32_t wb = wbuf0 + (uint32_t)(l & 1) * LAYER_BYTES;
        if (l < 3) {  // prefetch next layer's weights
            const uint8_t* src = (const uint8_t*)(g_Wp + (size_t)(l + 1) * 2 * 128 * KPAD);
            uint32_t dst = wbuf0 + (uint32_t)((l + 1) & 1) * LAYER_BYTES;
            for (int i = tid; i < LAYER_BYTES / 16; i += 256)
                cp16(dst + (uint32_t)i * 16, src + i * 16);
            CP_COMMIT();
            CP_WAIT(1);
        } else {
            CP_WAIT(0);
        }
        __syncthreads();  // weights ready; prev epilogue STS / encoding visible

        float acc[2][8][4];
        #pragma unroll
        for (int mt = 0; mt < 2; mt++)
            #pragma unroll
            for (int nt = 0; nt < 8; nt++)
                #pragma unroll
                for (int j = 0; j < 4; j++) acc[mt][nt][j] = 0.0f;

        #pragma unroll 1
        for (int ps = 0; ps < 3; ps++) {  // hi*hi, lo*hi, hi*lo
            uint32_t Ab = (ps == 1) ? Alo : Ahi;
            uint32_t Wb = wb + ((ps == 2) ? (uint32_t)HALF_BYTES : 0u);
            #pragma unroll
            for (int ks = 0; ks < 8; ks++) {
                uint32_t af[2][4], bf[4][4];
                ldsm4(af[0], Ab + aoff[0] + (uint32_t)ks * 32);
                ldsm4(af[1], Ab + aoff[1] + (uint32_t)ks * 32);
                #pragma unroll
                for (int q = 0; q < 4; q++)
                    ldsm4(bf[q], Wb + boff[q] + (uint32_t)ks * 32);
                #pragma unroll
                for (int mt = 0; mt < 2; mt++)
                    #pragma unroll
                    for (int nt = 0; nt < 8; nt++)
                        mma16816(acc[mt][nt], af[mt], &bf[nt >> 1][(nt & 1) * 2]);
            }
        }
        __syncthreads();  // all reads of A done before overwrite

        if (l < 3) {
            // ReLU + hi/lo split back into A
            #pragma unroll
            for (int mt = 0; mt < 2; mt++) {
                uint32_t r0 = (uint32_t)(warpm * 32 + mt * 16 + (lid >> 2));
                #pragma unroll
                for (int nt = 0; nt < 8; nt++) {
                    uint32_t cb = (uint32_t)(warpn * 64 + nt * 8 + (lid & 3) * 2) * 2;
                    uint32_t off = r0 * ROWB + cb;
                    float h0 = fmaxf(acc[mt][nt][0], 0.0f);
                    float h1 = fmaxf(acc[mt][nt][1], 0.0f);
                    uint32_t hp = pack_bf16x2(h0, h1);
                    sts32(Ahi + off, hp);
                    sts32(Alo + off, pack_bf16x2(h0 - lo_f(hp), h1 - hi_f(hp)));
                    float h2 = fmaxf(acc[mt][nt][2], 0.0f);
                    float h3 = fmaxf(acc[mt][nt][3], 0.0f);
                    uint32_t off8 = off + 8 * ROWB;
                    uint32_t hp2 = pack_bf16x2(h2, h3);
                    sts32(Ahi + off8, hp2);
                    sts32(Alo + off8, pack_bf16x2(h2 - lo_f(hp2), h3 - hi_f(hp2)));
                }
            }
        } else {
            // fused final layer: C = relu(h) . W_out
            float v[4] = {0.f, 0.f, 0.f, 0.f};
            #pragma unroll
            for (int mt = 0; mt < 2; mt++)
                #pragma unroll
                for (int nt = 0; nt < 8; nt++) {
                    int n = warpn * 64 + nt * 8 + (lid & 3) * 2;
                    float w0 = sWo[n], w1 = sWo[n + 1];
                    v[mt * 2]     += fmaxf(acc[mt][nt][0], 0.f) * w0
                                   + fmaxf(acc[mt][nt][1], 0.f) * w1;
                    v[mt * 2 + 1] += fmaxf(acc[mt][nt][2], 0.f) * w0
                                   + fmaxf(acc[mt][nt][3], 0.f) * w1;
                }
            #pragma unroll
            for (int i = 0; i < 4; i++) {
                v[i] += __shfl_xor_sync(0xffffffffu, v[i], 1);
                v[i] += __shfl_xor_sync(0xffffffffu, v[i], 2);
            }
            int rbase = warpm * 32 + (lid >> 2);
            if (warpn == 0 && (lid & 3) == 0) {
                sRed[rbase]      = v[0];
                sRed[rbase + 8]  = v[1];
                sRed[rbase + 16] = v[2];
                sRed[rbase + 24] = v[3];
            }
            __syncthreads();
            if (warpn == 1 && (lid & 3) == 0) {
                C_out[p0 + rbase]      = sRed[rbase]      + v[0];
                C_out[p0 + rbase + 8]  = sRed[rbase + 8]  + v[1];
                C_out[p0 + rbase + 16] = sRed[rbase + 16] + v[2];
                C_out[p0 + rbase + 24] = sRed[rbase + 24] + v[3];
            }
        }
    }
}

// ---------------- prep: V0, obj box filter, Cs ----------------
__global__ void prep_kernel(const int* __restrict__ bt,
                            const float* __restrict__ bc,
                            const float* __restrict__ C)
{
    int p = blockIdx.x * blockDim.x + threadIdx.x;
    if (p >= NPTS) return;
    int y = p >> 9;
    int xx = p & 511;
    bool is_free = (bt[p] == 0);

    float extra = 0.0f;
    if (is_free) {
        float sum = 0.0f;
        #pragma unroll
        for (int dy = -2; dy <= 2; dy++) {
            int yy = y + dy;
            if (yy < 0 || yy >= RES_H) continue;
            #pragma unroll
            for (int dx = -2; dx <= 2; dx++) {
                int xn = xx + dx;
                if (xn < 0 || xn >= RES_W) continue;
                int q = yy * RES_W + xn;
                int b = bt[q];
                float v = bc[q];
                if (b == 1 && v > 0.0f) sum += v;
            }
        }
        extra = sum * (1.0f / 25.0f);
    }
    g_Cs[p] = fmaxf(C[p], 0.0f) + extra;
    g_V[0][p] = is_free ? MAX_VAL : bc[p];
}

// ---------------- Jacobi stencil pass ----------------
__global__ void jacobi_kernel(int src,
                              const int* __restrict__ bt,
                              const float* __restrict__ bc)
{
    int p = blockIdx.x * blockDim.x + threadIdx.x;
    if (p >= NPTS) return;
    const float* __restrict__ Vin = g_V[src];
    float* __restrict__ Vout = g_V[1 - src];

    if (bt[p] != 0) { Vout[p] = bc[p]; return; }

    int y = p >> 9;
    int xx = p & 511;
    int ym = max(y - 1, 0), yp = min(y + 1, RES_H - 1);
    int xm = max(xx - 1, 0), xp = min(xx + 1, RES_W - 1);
    float nb = Vin[ym * RES_W + xm] + Vin[ym * RES_W + xx] + Vin[ym * RES_W + xp]
             + Vin[y  * RES_W + xm]                        + Vin[y  * RES_W + xp]
             + Vin[yp * RES_W + xm] + Vin[yp * RES_W + xx] + Vin[yp * RES_W + xp];
    Vout[p] = nb * 0.125f + g_Cs[p];
}

// ---------------- bilinear grid sample ----------------
__global__ void sample_kernel(const float* __restrict__ x,
                              float* __restrict__ out)
{
    int p = blockIdx.x * blockDim.x + threadIdx.x;
    if (p >= NPTS) return;
    const float* __restrict__ V = g_V[1];

    float gx = x[2 * p];
    float gy = x[2 * p + 1];
    float ix = fminf(fmaxf((gx + 1.0f) * 0.5f * (RES_W - 1), 0.0f), (float)(RES_W - 1));
    float iy = fminf(fmaxf((gy + 1.0f) * 0.5f * (RES_H - 1), 0.0f), (float)(RES_H - 1));
    int x0 = (int)floorf(ix);
    int y0 = (int)floorf(iy);
    int x1 = min(x0 + 1, RES_W - 1);
    int y1 = min(y0 + 1, RES_H - 1);
    float wx = ix - (float)x0;
    float wy = iy - (float)y0;

    float v00 = V[y0 * RES_W + x0];
    float v01 = V[y0 * RES_W + x1];
    float v10 = V[y1 * RES_W + x0];
    float v11 = V[y1 * RES_W + x1];
    out[p] = v00 * (1.0f - wx) * (1.0f - wy) + v01 * wx * (1.0f - wy)
           + v10 * (1.0f - wx) * wy + v11 * wx * wy;
}

// ---------------- launch ----------------
extern "C" void kernel_launch(void* const* d_in, const int* in_sizes, int n_in,
                              void* d_out, int out_size)
{
    const float* x    = (const float*)d_in[0];
    const int*   bt   = (const int*)  d_in[1];
    const float* bc   = (const float*)d_in[2];
    const float* Benc = (const float*)d_in[3];
    const float* Wh   = (const float*)d_in[4];
    const float* Wout = (const float*)d_in[5];

    float* out  = (float*)d_out;
    float* Cout = out + NPTS;

    cudaFuncSetAttribute(mlp_mma_kernel, cudaFuncAttributeMaxDynamicSharedMemorySize, DYN_BYTES);

    prepw_kernel<<<256, 256>>>(Wh);
    mlp_mma_kernel<<<NPTS / 128, 256, DYN_BYTES>>>(x, Benc, Wout, Cout);
    prep_kernel<<<NPTS / 256, 256>>>(bt, bc, Cout);
    for (int i = 0; i < N_ITERS; i++)
        jacobi_kernel<<<NPTS / 256, 256>>>(i & 1, bt, bc);
    sample_kernel<<<NPTS / 256, 256>>>(x, out);
}